// round 5
// baseline (speedup 1.0000x reference)
#include <cuda_runtime.h>
#include <math.h>

#define Bb 2
#define Ss 2048
#define Dd 1024
#define Hh 16
#define DH 64
#define BHN (Bb*Hh)

// ---------------- scratch (static device globals; no allocs) ----------------
__device__ float g_Q[(size_t)BHN * Ss * DH];     // [b*H+h][s][dh]
__device__ float g_K[(size_t)BHN * Ss * DH];
__device__ float g_V[(size_t)BHN * Ss * DH];
__device__ float g_ctx[(size_t)Bb * Ss * Dd];    // [b][s][h*dh+d]
__device__ float g_bias[Bb * Ss];                // 0 or -1e30 per (b, kv)
__device__ int   g_elem4;                        // 1 if mask elements are 4 bytes

// ---------------- mask dtype detection ----------------
// If mask is stored as 4-byte elements (int32 bool or float32), every one of
// the first 1024 words is in {0, 1, 0x3f800000}. If stored as 1-byte bools,
// words are packed groups of 4 bools (~90% ones) and violate that set.
// 1024 words is safe to read under both layouts (1-byte => 4096 B total).
__global__ void detect_mask_kernel(const unsigned int* __restrict__ m) {
    __shared__ int bad;
    if (threadIdx.x == 0) bad = 0;
    __syncthreads();
    int loc = 0;
    for (int i = threadIdx.x; i < 1024; i += blockDim.x) {
        unsigned int w = m[i];
        if (!(w == 0u || w == 1u || w == 0x3f800000u)) loc = 1;
    }
    if (loc) atomicExch(&bad, 1);
    __syncthreads();
    if (threadIdx.x == 0) g_elem4 = bad ? 0 : 1;
}

__global__ void build_bias_kernel(const void* __restrict__ mask) {
    int i = blockIdx.x * blockDim.x + threadIdx.x;
    if (i >= Bb * Ss) return;
    bool t;
    if (g_elem4) t = (((const unsigned int*)mask)[i] != 0u);
    else         t = (((const unsigned char*)mask)[i] != 0);
    g_bias[i] = t ? 0.0f : -1e30f;
}

// ---------------- QKV GEMM ----------------
// C[4096,3072] = inputs[4096,1024] @ Wqkv[3072,1024]^T + bqkv
// Tile 64x64x16, 256 threads (16x16), 4x4 per thread, k-major smem (float4 LDS).
// Epilogue scatters into g_Q/g_K/g_V with [bh][s][dh] layout.
__global__ void qkv_gemm_kernel(const float* __restrict__ A,
                                const float* __restrict__ W,
                                const float* __restrict__ bias) {
    __shared__ float As[16 * 68];
    __shared__ float Bs[16 * 68];
    const int tx = threadIdx.x, ty = threadIdx.y;
    const int tid = ty * 16 + tx;
    const int row0 = blockIdx.y * 64, col0 = blockIdx.x * 64;
    const int lr = tid >> 2, lc4 = tid & 3;

    float acc[4][4] = {};
    const float* Aptr = A + (size_t)(row0 + lr) * Dd + lc4 * 4;
    const float* Wptr = W + (size_t)(col0 + lr) * Dd + lc4 * 4;

    for (int k0 = 0; k0 < Dd; k0 += 16) {
        float4 av = *(const float4*)(Aptr + k0);
        float4 wv = *(const float4*)(Wptr + k0);
        __syncthreads();
        As[(lc4 * 4 + 0) * 68 + lr] = av.x;
        As[(lc4 * 4 + 1) * 68 + lr] = av.y;
        As[(lc4 * 4 + 2) * 68 + lr] = av.z;
        As[(lc4 * 4 + 3) * 68 + lr] = av.w;
        Bs[(lc4 * 4 + 0) * 68 + lr] = wv.x;
        Bs[(lc4 * 4 + 1) * 68 + lr] = wv.y;
        Bs[(lc4 * 4 + 2) * 68 + lr] = wv.z;
        Bs[(lc4 * 4 + 3) * 68 + lr] = wv.w;
        __syncthreads();
#pragma unroll
        for (int k = 0; k < 16; k++) {
            float4 a = *(const float4*)&As[k * 68 + ty * 4];
            float4 b = *(const float4*)&Bs[k * 68 + tx * 4];
            acc[0][0] += a.x * b.x; acc[0][1] += a.x * b.y; acc[0][2] += a.x * b.z; acc[0][3] += a.x * b.w;
            acc[1][0] += a.y * b.x; acc[1][1] += a.y * b.y; acc[1][2] += a.y * b.z; acc[1][3] += a.y * b.w;
            acc[2][0] += a.z * b.x; acc[2][1] += a.z * b.y; acc[2][2] += a.z * b.z; acc[2][3] += a.z * b.w;
            acc[3][0] += a.w * b.x; acc[3][1] += a.w * b.y; acc[3][2] += a.w * b.z; acc[3][3] += a.w * b.w;
        }
    }
    // Each 64-col block lies entirely within one (head, q/k/v) segment (192 = 3*64).
    const int h    = col0 / 192;
    const int rseg = col0 - h * 192;
    const int part = rseg >> 6;             // 0=q 1=k 2=v
    float* dst = (part == 0) ? g_Q : (part == 1) ? g_K : g_V;
#pragma unroll
    for (int i = 0; i < 4; i++) {
        int row = row0 + ty * 4 + i;
        int b = row >> 11, s = row & 2047;
        size_t base = ((size_t)(b * Hh + h) * Ss + s) * DH;
#pragma unroll
        for (int j = 0; j < 4; j++) {
            int col = col0 + tx * 4 + j;
            int d = col & 63;
            dst[base + d] = acc[i][j] + bias[col];
        }
    }
}

// ---------------- Flash attention (fp32) ----------------
// grid: (S/64, B*H). 256 threads (16x16), 4x4 per thread, 64x64 kv tiles,
// online softmax. ALiBi + key mask bias applied to logits.
#define ATTN_SMEM_FLOATS (64*64 + 64*68 + 64*68 + 64*68 + 64)
__global__ void attn_kernel() {
    extern __shared__ float sm[];
    float* Qt = sm;                       // [d*64 + qi]
    float* Kt = Qt + 64 * 64;             // [d*68 + kj]
    float* Vs = Kt + 64 * 68;             // [kv*68 + d]
    float* Pt = Vs + 64 * 68;             // [kj*68 + qi]
    float* bs = Pt + 64 * 68;             // [64] key-mask bias tile

    const int tx = threadIdx.x, ty = threadIdx.y;
    const int tid = ty * 16 + tx;
    const int bh = blockIdx.y;
    const int b = bh >> 4, h = bh & 15;
    const int q0 = blockIdx.x * 64;

    const float* Qg = g_Q + ((size_t)bh * Ss + q0) * DH;
    const float* Kg = g_K + (size_t)bh * Ss * DH;
    const float* Vg = g_V + (size_t)bh * Ss * DH;
    const float slope = exp2f(-0.5f * (float)(h + 1));
    const float scale = 0.03125f;  // 1024^-0.5

    // load Q tile transposed (once)
#pragma unroll
    for (int u = 0; u < 4; u++) {
        int fl = u * 256 + tid;
        int r = fl & 63, dq = fl >> 6;
        float4 v = *(const float4*)(Qg + (size_t)r * DH + dq * 4);
        Qt[(dq * 4 + 0) * 64 + r] = v.x;
        Qt[(dq * 4 + 1) * 64 + r] = v.y;
        Qt[(dq * 4 + 2) * 64 + r] = v.z;
        Qt[(dq * 4 + 3) * 64 + r] = v.w;
    }

    float m_[4], l_[4], acc[4][4];
#pragma unroll
    for (int i = 0; i < 4; i++) {
        m_[i] = -3.0e38f; l_[i] = 0.0f;
#pragma unroll
        for (int j = 0; j < 4; j++) acc[i][j] = 0.0f;
    }

    for (int t = 0; t < Ss / 64; t++) {
        __syncthreads();  // prior-iteration reads of Kt/Vs/Pt/bs complete
        const float* Kg_t = Kg + (size_t)t * 64 * DH;
        const float* Vg_t = Vg + (size_t)t * 64 * DH;
#pragma unroll
        for (int u = 0; u < 4; u++) {     // K transposed
            int fl = u * 256 + tid;
            int r = fl & 63, dq = fl >> 6;
            float4 v = *(const float4*)(Kg_t + (size_t)r * DH + dq * 4);
            Kt[(dq * 4 + 0) * 68 + r] = v.x;
            Kt[(dq * 4 + 1) * 68 + r] = v.y;
            Kt[(dq * 4 + 2) * 68 + r] = v.z;
            Kt[(dq * 4 + 3) * 68 + r] = v.w;
        }
#pragma unroll
        for (int u = 0; u < 4; u++) {     // V natural
            int fl = u * 256 + tid;
            int r = fl >> 4, c4 = fl & 15;
            *(float4*)&Vs[r * 68 + c4 * 4] =
                *(const float4*)(Vg_t + (size_t)r * DH + c4 * 4);
        }
        if (tid < 64) bs[tid] = g_bias[b * Ss + t * 64 + tid];
        __syncthreads();

        // S = Q K^T
        float sv[4][4] = {};
#pragma unroll
        for (int d = 0; d < 64; d++) {
            float4 a = *(const float4*)&Qt[d * 64 + ty * 4];
            float4 kk = *(const float4*)&Kt[d * 68 + tx * 4];
            sv[0][0] += a.x * kk.x; sv[0][1] += a.x * kk.y; sv[0][2] += a.x * kk.z; sv[0][3] += a.x * kk.w;
            sv[1][0] += a.y * kk.x; sv[1][1] += a.y * kk.y; sv[1][2] += a.y * kk.z; sv[1][3] += a.y * kk.w;
            sv[2][0] += a.z * kk.x; sv[2][1] += a.z * kk.y; sv[2][2] += a.z * kk.z; sv[2][3] += a.z * kk.w;
            sv[3][0] += a.w * kk.x; sv[3][1] += a.w * kk.y; sv[3][2] += a.w * kk.z; sv[3][3] += a.w * kk.w;
        }

        // logits + online softmax (row stats across the 16 x-lanes)
#pragma unroll
        for (int i = 0; i < 4; i++) {
            int q = q0 + ty * 4 + i;
            float rowmax = -3.0e38f;
#pragma unroll
            for (int j = 0; j < 4; j++) {
                int kv = t * 64 + tx * 4 + j;
                float val = sv[i][j] * scale
                          + slope * (-fabsf((float)(q - kv)))
                          + bs[tx * 4 + j];
                sv[i][j] = val;
                rowmax = fmaxf(rowmax, val);
            }
#pragma unroll
            for (int off = 1; off < 16; off <<= 1)
                rowmax = fmaxf(rowmax, __shfl_xor_sync(0xffffffffu, rowmax, off));
            float newm = fmaxf(m_[i], rowmax);
            float corr = __expf(m_[i] - newm);
            float rsum = 0.0f;
#pragma unroll
            for (int j = 0; j < 4; j++) {
                float p = __expf(sv[i][j] - newm);
                Pt[(tx * 4 + j) * 68 + ty * 4 + i] = p;
                rsum += p;
            }
#pragma unroll
            for (int off = 1; off < 16; off <<= 1)
                rsum += __shfl_xor_sync(0xffffffffu, rsum, off);
            l_[i] = l_[i] * corr + rsum;
            m_[i] = newm;
#pragma unroll
            for (int j = 0; j < 4; j++) acc[i][j] *= corr;
        }
        __syncthreads();

        // O += P V
#pragma unroll
        for (int k = 0; k < 64; k++) {
            float4 a = *(const float4*)&Pt[k * 68 + ty * 4];
            float4 vv = *(const float4*)&Vs[k * 68 + tx * 4];
            acc[0][0] += a.x * vv.x; acc[0][1] += a.x * vv.y; acc[0][2] += a.x * vv.z; acc[0][3] += a.x * vv.w;
            acc[1][0] += a.y * vv.x; acc[1][1] += a.y * vv.y; acc[1][2] += a.y * vv.z; acc[1][3] += a.y * vv.w;
            acc[2][0] += a.z * vv.x; acc[2][1] += a.z * vv.y; acc[2][2] += a.z * vv.z; acc[2][3] += a.z * vv.w;
            acc[3][0] += a.w * vv.x; acc[3][1] += a.w * vv.y; acc[3][2] += a.w * vv.z; acc[3][3] += a.w * vv.w;
        }
    }

    // normalize and write ctx[b][s][h*64+d]
#pragma unroll
    for (int i = 0; i < 4; i++) {
        int q = q0 + ty * 4 + i;
        float inv = 1.0f / l_[i];
        size_t base = ((size_t)(b * Ss + q)) * Dd + h * DH;
#pragma unroll
        for (int j = 0; j < 4; j++)
            g_ctx[base + tx * 4 + j] = acc[i][j] * inv;
    }
}

// ---------------- Proj GEMM ----------------
// out[4096,1024] = g_ctx[4096,1024] @ Wproj[1024,1024]^T + bproj
__global__ void proj_gemm_kernel(const float* __restrict__ W,
                                 const float* __restrict__ bias,
                                 float* __restrict__ out) {
    __shared__ float As[16 * 68];
    __shared__ float Bs[16 * 68];
    const int tx = threadIdx.x, ty = threadIdx.y;
    const int tid = ty * 16 + tx;
    const int row0 = blockIdx.y * 64, col0 = blockIdx.x * 64;
    const int lr = tid >> 2, lc4 = tid & 3;

    float acc[4][4] = {};
    const float* Aptr = g_ctx + (size_t)(row0 + lr) * Dd + lc4 * 4;
    const float* Wptr = W + (size_t)(col0 + lr) * Dd + lc4 * 4;

    for (int k0 = 0; k0 < Dd; k0 += 16) {
        float4 av = *(const float4*)(Aptr + k0);
        float4 wv = *(const float4*)(Wptr + k0);
        __syncthreads();
        As[(lc4 * 4 + 0) * 68 + lr] = av.x;
        As[(lc4 * 4 + 1) * 68 + lr] = av.y;
        As[(lc4 * 4 + 2) * 68 + lr] = av.z;
        As[(lc4 * 4 + 3) * 68 + lr] = av.w;
        Bs[(lc4 * 4 + 0) * 68 + lr] = wv.x;
        Bs[(lc4 * 4 + 1) * 68 + lr] = wv.y;
        Bs[(lc4 * 4 + 2) * 68 + lr] = wv.z;
        Bs[(lc4 * 4 + 3) * 68 + lr] = wv.w;
        __syncthreads();
#pragma unroll
        for (int k = 0; k < 16; k++) {
            float4 a = *(const float4*)&As[k * 68 + ty * 4];
            float4 b = *(const float4*)&Bs[k * 68 + tx * 4];
            acc[0][0] += a.x * b.x; acc[0][1] += a.x * b.y; acc[0][2] += a.x * b.z; acc[0][3] += a.x * b.w;
            acc[1][0] += a.y * b.x; acc[1][1] += a.y * b.y; acc[1][2] += a.y * b.z; acc[1][3] += a.y * b.w;
            acc[2][0] += a.z * b.x; acc[2][1] += a.z * b.y; acc[2][2] += a.z * b.z; acc[2][3] += a.z * b.w;
            acc[3][0] += a.w * b.x; acc[3][1] += a.w * b.y; acc[3][2] += a.w * b.z; acc[3][3] += a.w * b.w;
        }
    }
#pragma unroll
    for (int i = 0; i < 4; i++) {
        int row = row0 + ty * 4 + i;
#pragma unroll
        for (int j = 0; j < 4; j++) {
            int col = col0 + tx * 4 + j;
            out[(size_t)row * Dd + col] = acc[i][j] + bias[col];
        }
    }
}

// ---------------- launch ----------------
extern "C" void kernel_launch(void* const* d_in, const int* in_sizes, int n_in,
                              void* d_out, int out_size) {
    const float* inputs = (const float*)d_in[0];
    const void*  mask   = d_in[1];
    const float* Wqkv   = (const float*)d_in[2];
    const float* bqkv   = (const float*)d_in[3];
    const float* Wproj  = (const float*)d_in[4];
    const float* bproj  = (const float*)d_in[5];
    float* out = (float*)d_out;

    cudaFuncSetAttribute(attn_kernel, cudaFuncAttributeMaxDynamicSharedMemorySize,
                         ATTN_SMEM_FLOATS * (int)sizeof(float));

    detect_mask_kernel<<<1, 256>>>((const unsigned int*)mask);
    build_bias_kernel<<<(Bb * Ss + 255) / 256, 256>>>(mask);
    qkv_gemm_kernel<<<dim3(3 * Dd / 64, Bb * Ss / 64), dim3(16, 16)>>>(inputs, Wqkv, bqkv);
    attn_kernel<<<dim3(Ss / 64, BHN), dim3(16, 16),
                  ATTN_SMEM_FLOATS * sizeof(float)>>>();
    proj_gemm_kernel<<<dim3(Dd / 64, Bb * Ss / 64), dim3(16, 16)>>>(Wproj, bproj, out);
}

// round 12
// speedup vs baseline: 1.3473x; 1.3473x over previous
#include <cuda_runtime.h>
#include <cuda_bf16.h>
#include <math.h>
#include <stdint.h>

#define Bb 2
#define Ss 2048
#define Dd 1024
#define Hh 16
#define DH 64
#define BHN (Bb*Hh)

// ---------------- scratch (static device globals; no allocs) ----------------
__device__ float g_Q[(size_t)BHN * Ss * DH];     // [b*H+h][s][dh]
__device__ float g_K[(size_t)BHN * Ss * DH];
__device__ float g_V[(size_t)BHN * Ss * DH];
__device__ float g_ctx[(size_t)Bb * Ss * Dd];    // [b][s][h*dh+d]
__device__ float g_bias[Bb * Ss];                // 0 or -1e30 per (b, kv)
__device__ int   g_elem4;                        // 1 if mask elements are 4 bytes

// bf16 hi/lo split buffers for tensor-core GEMMs
__device__ __nv_bfloat16 g_Ah[(size_t)Bb * Ss * Dd];
__device__ __nv_bfloat16 g_Al[(size_t)Bb * Ss * Dd];
__device__ __nv_bfloat16 g_WQh[(size_t)3 * Dd * Dd];
__device__ __nv_bfloat16 g_WQl[(size_t)3 * Dd * Dd];
__device__ __nv_bfloat16 g_WPh[(size_t)Dd * Dd];
__device__ __nv_bfloat16 g_WPl[(size_t)Dd * Dd];
__device__ __nv_bfloat16 g_Ch[(size_t)Bb * Ss * Dd];
__device__ __nv_bfloat16 g_Cl[(size_t)Bb * Ss * Dd];

// ---------------- mask dtype detection ----------------
__global__ void detect_mask_kernel(const unsigned int* __restrict__ m) {
    __shared__ int bad;
    if (threadIdx.x == 0) bad = 0;
    __syncthreads();
    int loc = 0;
    for (int i = threadIdx.x; i < 1024; i += blockDim.x) {
        unsigned int w = m[i];
        if (!(w == 0u || w == 1u || w == 0x3f800000u)) loc = 1;
    }
    if (loc) atomicExch(&bad, 1);
    __syncthreads();
    if (threadIdx.x == 0) g_elem4 = bad ? 0 : 1;
}

__global__ void build_bias_kernel(const void* __restrict__ mask) {
    int i = blockIdx.x * blockDim.x + threadIdx.x;
    if (i >= Bb * Ss) return;
    bool t;
    if (g_elem4) t = (((const unsigned int*)mask)[i] != 0u);
    else         t = (((const unsigned char*)mask)[i] != 0);
    g_bias[i] = t ? 0.0f : -1e30f;
}

// ---------------- fp32 -> bf16 hi/lo split ----------------
__global__ void split_kernel(const float* __restrict__ src,
                             __nv_bfloat16* __restrict__ hi,
                             __nv_bfloat16* __restrict__ lo, int n) {
    int i = blockIdx.x * blockDim.x + threadIdx.x;
    if (i >= n) return;
    float x = src[i];
    __nv_bfloat16 h = __float2bfloat16(x);
    hi[i] = h;
    lo[i] = __float2bfloat16(x - __bfloat162float(h));
}

// ---------------- warp-level bf16 MMA (sm_80+ path; no 'a'-arch needed) ----
__device__ __forceinline__ void mma_bf16_16816(float* d, const uint32_t* a,
                                               const uint32_t* b) {
    asm volatile(
        "mma.sync.aligned.m16n8k16.row.col.f32.bf16.bf16.f32 "
        "{%0,%1,%2,%3}, {%4,%5,%6,%7}, {%8,%9}, {%0,%1,%2,%3};"
        : "+f"(d[0]), "+f"(d[1]), "+f"(d[2]), "+f"(d[3])
        : "r"(a[0]), "r"(a[1]), "r"(a[2]), "r"(a[3]), "r"(b[0]), "r"(b[1]));
}

// ---------------- mma.sync GEMM: C[M,N] = A[M,K] @ B[N,K]^T (+bias) -------
// hi/lo split, 3 passes (AhBh + AhBl + AlBh), fp32 accumulators in registers.
// Block tile 128x128, k-chunk 32. 8 warps: 4(M) x 2(N), warp tile 32x64.
// smem rows padded to 40 bf16 (20 b32 words): the 8-row x 4-word fragment
// access pattern maps to 32 distinct banks (20*r+c mod 32 all distinct).
#define KTOT 1024
#define KC 32
#define PADW 40           // bf16 per padded row
#define PADW32 (PADW/2)   // b32 words per row
// MODE 0: QKV epilogue (scatter to g_Q/g_K/g_V, +bqkv). MODE 1: proj (+bproj).
template <int MODE>
__global__ void __launch_bounds__(256, 2)
mma_gemm_kernel(const __nv_bfloat16* __restrict__ Ah,
                const __nv_bfloat16* __restrict__ Al,
                const __nv_bfloat16* __restrict__ Bh,
                const __nv_bfloat16* __restrict__ Bl,
                const float* __restrict__ bias,
                float* __restrict__ out) {
    __shared__ __nv_bfloat16 sA[2][128 * PADW];   // [hi/lo][128 rows x 32 k]
    __shared__ __nv_bfloat16 sB[2][128 * PADW];

    const int tid = threadIdx.x;
    const int wid = tid >> 5, lane = tid & 31;
    const int wm = wid >> 1;          // 0..3  (M quadrant, 32 rows)
    const int wn = wid & 1;           // 0..1  (N half, 64 cols)
    const int row0 = blockIdx.y * 128;
    const int col0 = blockIdx.x * 128;

    const __nv_bfloat16* srcA[2] = { Ah + (size_t)row0 * KTOT, Al + (size_t)row0 * KTOT };
    const __nv_bfloat16* srcB[2] = { Bh + (size_t)col0 * KTOT, Bl + (size_t)col0 * KTOT };

    float acc[2][8][4];
#pragma unroll
    for (int mt = 0; mt < 2; mt++)
#pragma unroll
        for (int nt = 0; nt < 8; nt++)
#pragma unroll
            for (int e = 0; e < 4; e++) acc[mt][nt][e] = 0.0f;

    const int r0 = lane >> 2;         // fragment row within 8-row group
    const int kw = lane & 3;          // fragment k-word (b32) index

    for (int ch = 0; ch < KTOT / KC; ch++) {
        const int k0 = ch * KC;
        __syncthreads();   // previous chunk's fragment reads complete
        // fill 4 tiles: each 128 rows x 32 bf16 (=4 uint4 per row), 512 uint4
#pragma unroll
        for (int t = 0; t < 4; t++) {
            const __nv_bfloat16* src = (t < 2) ? srcA[t] : srcB[t - 2];
            uint4* dst = (uint4*)((t < 2) ? sA[t] : sB[t - 2]);
#pragma unroll
            for (int u = 0; u < 2; u++) {
                int idx = u * 256 + tid;
                int r = idx >> 2, c = idx & 3;
                dst[r * 5 + c] = *(const uint4*)(src + (size_t)r * KTOT + k0 + c * 8);
            }
        }
        __syncthreads();

        // 3 split passes over this chunk
#pragma unroll
        for (int ps = 0; ps < 3; ps++) {
            const int ia = (ps == 2) ? 1 : 0;   // (h,h), (h,l), (l,h)
            const int ib = (ps == 1) ? 1 : 0;
            const uint32_t* wa = (const uint32_t*)sA[ia];
            const uint32_t* wb = (const uint32_t*)sB[ib];
#pragma unroll
            for (int ks = 0; ks < 2; ks++) {
                const int k8 = ks * 8;          // b32 word offset of this k16
                uint32_t af[2][4];
#pragma unroll
                for (int mt = 0; mt < 2; mt++) {
                    int rb = wm * 32 + mt * 16;
                    af[mt][0] = wa[(rb + r0)      * PADW32 + k8 + kw];
                    af[mt][1] = wa[(rb + r0 + 8)  * PADW32 + k8 + kw];
                    af[mt][2] = wa[(rb + r0)      * PADW32 + k8 + kw + 4];
                    af[mt][3] = wa[(rb + r0 + 8)  * PADW32 + k8 + kw + 4];
                }
#pragma unroll
                for (int nt = 0; nt < 8; nt++) {
                    int nb = wn * 64 + nt * 8;
                    uint32_t bf[2];
                    bf[0] = wb[(nb + r0) * PADW32 + k8 + kw];
                    bf[1] = wb[(nb + r0) * PADW32 + k8 + kw + 4];
#pragma unroll
                    for (int mt = 0; mt < 2; mt++)
                        mma_bf16_16816(acc[mt][nt], af[mt], bf);
                }
            }
        }
    }

    // epilogue: acc[mt][nt][e]: rows = row0+wm*32+mt*16+lane/4 (+8 for e>=2),
    //           cols = col0+wn*64+nt*8+2*(lane%4) (+1 for odd e)
#pragma unroll
    for (int mt = 0; mt < 2; mt++) {
#pragma unroll
        for (int e2 = 0; e2 < 2; e2++) {            // 0: rows +0, 1: rows +8
            int row = row0 + wm * 32 + mt * 16 + (lane >> 2) + e2 * 8;
            const int b = row >> 11, s = row & 2047;
#pragma unroll
            for (int nt = 0; nt < 8; nt++) {
#pragma unroll
                for (int e1 = 0; e1 < 2; e1++) {    // col pair
                    int col = col0 + wn * 64 + nt * 8 + 2 * (lane & 3) + e1;
                    float val = acc[mt][nt][e2 * 2 + e1] + bias[col];
                    if (MODE == 0) {
                        int h = col / 192;
                        int rem = col - h * 192;
                        int part = rem >> 6;
                        int d = rem & 63;
                        float* dst = (part == 0) ? g_Q : (part == 1) ? g_K : g_V;
                        dst[((size_t)(b * Hh + h) * Ss + s) * DH + d] = val;
                    } else {
                        out[(size_t)row * Dd + col] = val;
                    }
                }
            }
        }
    }
}

// ---------------- Flash attention (fp32, unchanged from passing baseline) --
#define ATTN_SMEM_FLOATS (64*64 + 64*68 + 64*68 + 64*68 + 64)
__global__ void attn_kernel() {
    extern __shared__ float sm[];
    float* Qt = sm;                       // [d*64 + qi]
    float* Kt = Qt + 64 * 64;             // [d*68 + kj]
    float* Vs = Kt + 64 * 68;             // [kv*68 + d]
    float* Pt = Vs + 64 * 68;             // [kj*68 + qi]
    float* bs = Pt + 64 * 68;             // [64] key-mask bias tile

    const int tx = threadIdx.x, ty = threadIdx.y;
    const int tid = ty * 16 + tx;
    const int bh = blockIdx.y;
    const int b = bh >> 4, h = bh & 15;
    const int q0 = blockIdx.x * 64;

    const float* Qg = g_Q + ((size_t)bh * Ss + q0) * DH;
    const float* Kg = g_K + (size_t)bh * Ss * DH;
    const float* Vg = g_V + (size_t)bh * Ss * DH;
    const float slope = exp2f(-0.5f * (float)(h + 1));
    const float scale = 0.03125f;  // 1024^-0.5

#pragma unroll
    for (int u = 0; u < 4; u++) {
        int fl = u * 256 + tid;
        int r = fl & 63, dq = fl >> 6;
        float4 v = *(const float4*)(Qg + (size_t)r * DH + dq * 4);
        Qt[(dq * 4 + 0) * 64 + r] = v.x;
        Qt[(dq * 4 + 1) * 64 + r] = v.y;
        Qt[(dq * 4 + 2) * 64 + r] = v.z;
        Qt[(dq * 4 + 3) * 64 + r] = v.w;
    }

    float m_[4], l_[4], acc[4][4];
#pragma unroll
    for (int i = 0; i < 4; i++) {
        m_[i] = -3.0e38f; l_[i] = 0.0f;
#pragma unroll
        for (int j = 0; j < 4; j++) acc[i][j] = 0.0f;
    }

    for (int t = 0; t < Ss / 64; t++) {
        __syncthreads();
        const float* Kg_t = Kg + (size_t)t * 64 * DH;
        const float* Vg_t = Vg + (size_t)t * 64 * DH;
#pragma unroll
        for (int u = 0; u < 4; u++) {
            int fl = u * 256 + tid;
            int r = fl & 63, dq = fl >> 6;
            float4 v = *(const float4*)(Kg_t + (size_t)r * DH + dq * 4);
            Kt[(dq * 4 + 0) * 68 + r] = v.x;
            Kt[(dq * 4 + 1) * 68 + r] = v.y;
            Kt[(dq * 4 + 2) * 68 + r] = v.z;
            Kt[(dq * 4 + 3) * 68 + r] = v.w;
        }
#pragma unroll
        for (int u = 0; u < 4; u++) {
            int fl = u * 256 + tid;
            int r = fl >> 4, c4 = fl & 15;
            *(float4*)&Vs[r * 68 + c4 * 4] =
                *(const float4*)(Vg_t + (size_t)r * DH + c4 * 4);
        }
        if (tid < 64) bs[tid] = g_bias[b * Ss + t * 64 + tid];
        __syncthreads();

        float sv[4][4] = {};
#pragma unroll
        for (int d = 0; d < 64; d++) {
            float4 a = *(const float4*)&Qt[d * 64 + ty * 4];
            float4 kk = *(const float4*)&Kt[d * 68 + tx * 4];
            sv[0][0] += a.x * kk.x; sv[0][1] += a.x * kk.y; sv[0][2] += a.x * kk.z; sv[0][3] += a.x * kk.w;
            sv[1][0] += a.y * kk.x; sv[1][1] += a.y * kk.y; sv[1][2] += a.y * kk.z; sv[1][3] += a.y * kk.w;
            sv[2][0] += a.z * kk.x; sv[2][1] += a.z * kk.y; sv[2][2] += a.z * kk.z; sv[2][3] += a.z * kk.w;
            sv[3][0] += a.w * kk.x; sv[3][1] += a.w * kk.y; sv[3][2] += a.w * kk.z; sv[3][3] += a.w * kk.w;
        }

#pragma unroll
        for (int i = 0; i < 4; i++) {
            int q = q0 + ty * 4 + i;
            float rowmax = -3.0e38f;
#pragma unroll
            for (int j = 0; j < 4; j++) {
                int kv = t * 64 + tx * 4 + j;
                float val = sv[i][j] * scale
                          + slope * (-fabsf((float)(q - kv)))
                          + bs[tx * 4 + j];
                sv[i][j] = val;
                rowmax = fmaxf(rowmax, val);
            }
#pragma unroll
            for (int off = 1; off < 16; off <<= 1)
                rowmax = fmaxf(rowmax, __shfl_xor_sync(0xffffffffu, rowmax, off));
            float newm = fmaxf(m_[i], rowmax);
            float corr = __expf(m_[i] - newm);
            float rsum = 0.0f;
#pragma unroll
            for (int j = 0; j < 4; j++) {
                float p = __expf(sv[i][j] - newm);
                Pt[(tx * 4 + j) * 68 + ty * 4 + i] = p;
                rsum += p;
            }
#pragma unroll
            for (int off = 1; off < 16; off <<= 1)
                rsum += __shfl_xor_sync(0xffffffffu, rsum, off);
            l_[i] = l_[i] * corr + rsum;
            m_[i] = newm;
#pragma unroll
            for (int j = 0; j < 4; j++) acc[i][j] *= corr;
        }
        __syncthreads();

#pragma unroll
        for (int k = 0; k < 64; k++) {
            float4 a = *(const float4*)&Pt[k * 68 + ty * 4];
            float4 vv = *(const float4*)&Vs[k * 68 + tx * 4];
            acc[0][0] += a.x * vv.x; acc[0][1] += a.x * vv.y; acc[0][2] += a.x * vv.z; acc[0][3] += a.x * vv.w;
            acc[1][0] += a.y * vv.x; acc[1][1] += a.y * vv.y; acc[1][2] += a.y * vv.z; acc[1][3] += a.y * vv.w;
            acc[2][0] += a.z * vv.x; acc[2][1] += a.z * vv.y; acc[2][2] += a.z * vv.z; acc[2][3] += a.z * vv.w;
            acc[3][0] += a.w * vv.x; acc[3][1] += a.w * vv.y; acc[3][2] += a.w * vv.z; acc[3][3] += a.w * vv.w;
        }
    }

#pragma unroll
    for (int i = 0; i < 4; i++) {
        int q = q0 + ty * 4 + i;
        float inv = 1.0f / l_[i];
        size_t base = ((size_t)(b * Ss + q)) * Dd + h * DH;
#pragma unroll
        for (int j = 0; j < 4; j++)
            g_ctx[base + tx * 4 + j] = acc[i][j] * inv;
    }
}

// ---------------- launch ----------------
extern "C" void kernel_launch(void* const* d_in, const int* in_sizes, int n_in,
                              void* d_out, int out_size) {
    const float* inputs = (const float*)d_in[0];
    const void*  mask   = d_in[1];
    const float* Wqkv   = (const float*)d_in[2];
    const float* bqkv   = (const float*)d_in[3];
    const float* Wproj  = (const float*)d_in[4];
    const float* bproj  = (const float*)d_in[5];
    float* out = (float*)d_out;

    cudaFuncSetAttribute(attn_kernel, cudaFuncAttributeMaxDynamicSharedMemorySize,
                         ATTN_SMEM_FLOATS * (int)sizeof(float));

    // resolve device-global scratch addresses (host-side, graph-safe)
    __nv_bfloat16 *pAh, *pAl, *pWQh, *pWQl, *pWPh, *pWPl, *pCh, *pCl;
    float* pCtx;
    cudaGetSymbolAddress((void**)&pAh,  g_Ah);
    cudaGetSymbolAddress((void**)&pAl,  g_Al);
    cudaGetSymbolAddress((void**)&pWQh, g_WQh);
    cudaGetSymbolAddress((void**)&pWQl, g_WQl);
    cudaGetSymbolAddress((void**)&pWPh, g_WPh);
    cudaGetSymbolAddress((void**)&pWPl, g_WPl);
    cudaGetSymbolAddress((void**)&pCh,  g_Ch);
    cudaGetSymbolAddress((void**)&pCl,  g_Cl);
    cudaGetSymbolAddress((void**)&pCtx, g_ctx);

    detect_mask_kernel<<<1, 256>>>((const unsigned int*)mask);
    build_bias_kernel<<<(Bb * Ss + 255) / 256, 256>>>(mask);

    const int nA = Bb * Ss * Dd;        // 4194304
    const int nWQ = 3 * Dd * Dd;        // 3145728
    const int nWP = Dd * Dd;            // 1048576
    split_kernel<<<(nA + 255) / 256, 256>>>(inputs, pAh, pAl, nA);
    split_kernel<<<(nWQ + 255) / 256, 256>>>(Wqkv, pWQh, pWQl, nWQ);
    split_kernel<<<(nWP + 255) / 256, 256>>>(Wproj, pWPh, pWPl, nWP);

    mma_gemm_kernel<0><<<dim3(3 * Dd / 128, Bb * Ss / 128), 256>>>(
        pAh, pAl, pWQh, pWQl, bqkv, nullptr);

    attn_kernel<<<dim3(Ss / 64, BHN), dim3(16, 16),
                  ATTN_SMEM_FLOATS * sizeof(float)>>>();

    split_kernel<<<(nA + 255) / 256, 256>>>(pCtx, pCh, pCl, nA);
    mma_gemm_kernel<1><<<dim3(Dd / 128, Bb * Ss / 128), 256>>>(
        pCh, pCl, pWPh, pWPl, bproj, out);
}

// round 13
// speedup vs baseline: 2.1561x; 1.6004x over previous
#include <cuda_runtime.h>
#include <cuda_bf16.h>
#include <math.h>
#include <stdint.h>

#define Bb 2
#define Ss 2048
#define Dd 1024
#define Hh 16
#define DH 64
#define BHN (Bb*Hh)

// ---------------- scratch (static device globals; no allocs) ----------------
__device__ float g_Q[(size_t)BHN * Ss * DH];     // [b*H+h][s][dh]
__device__ float g_K[(size_t)BHN * Ss * DH];
__device__ float g_V[(size_t)BHN * Ss * DH];
__device__ float g_bias[Bb * Ss];                // 0 or -1e30 per (b, kv)
__device__ int   g_elem4;                        // 1 if mask elements are 4 bytes

// bf16 hi/lo split buffers for tensor-core GEMMs
__device__ __nv_bfloat16 g_Ah[(size_t)Bb * Ss * Dd];
__device__ __nv_bfloat16 g_Al[(size_t)Bb * Ss * Dd];
__device__ __nv_bfloat16 g_WQh[(size_t)3 * Dd * Dd];
__device__ __nv_bfloat16 g_WQl[(size_t)3 * Dd * Dd];
__device__ __nv_bfloat16 g_WPh[(size_t)Dd * Dd];
__device__ __nv_bfloat16 g_WPl[(size_t)Dd * Dd];
__device__ __nv_bfloat16 g_Ch[(size_t)Bb * Ss * Dd];   // attn output hi
__device__ __nv_bfloat16 g_Cl[(size_t)Bb * Ss * Dd];   // attn output lo

// ---------------- helpers ----------------
__device__ __forceinline__ uint32_t pack2(float lo, float hi) {
    uint32_t a = (uint32_t)__bfloat16_as_ushort(__float2bfloat16(lo));
    uint32_t bq = (uint32_t)__bfloat16_as_ushort(__float2bfloat16(hi));
    return a | (bq << 16);
}
__device__ __forceinline__ float bflo(float x) {   // residual after bf16 round
    return x - __bfloat162float(__float2bfloat16(x));
}
__device__ __forceinline__ void mma_bf16_16816(float* d, const uint32_t* a,
                                               const uint32_t* b) {
    asm volatile(
        "mma.sync.aligned.m16n8k16.row.col.f32.bf16.bf16.f32 "
        "{%0,%1,%2,%3}, {%4,%5,%6,%7}, {%8,%9}, {%0,%1,%2,%3};"
        : "+f"(d[0]), "+f"(d[1]), "+f"(d[2]), "+f"(d[3])
        : "r"(a[0]), "r"(a[1]), "r"(a[2]), "r"(a[3]), "r"(b[0]), "r"(b[1]));
}

// ---------------- mask dtype detection ----------------
__global__ void detect_mask_kernel(const unsigned int* __restrict__ m) {
    __shared__ int bad;
    if (threadIdx.x == 0) bad = 0;
    __syncthreads();
    int loc = 0;
    for (int i = threadIdx.x; i < 1024; i += blockDim.x) {
        unsigned int w = m[i];
        if (!(w == 0u || w == 1u || w == 0x3f800000u)) loc = 1;
    }
    if (loc) atomicExch(&bad, 1);
    __syncthreads();
    if (threadIdx.x == 0) g_elem4 = bad ? 0 : 1;
}

__global__ void build_bias_kernel(const void* __restrict__ mask) {
    int i = blockIdx.x * blockDim.x + threadIdx.x;
    if (i >= Bb * Ss) return;
    bool t;
    if (g_elem4) t = (((const unsigned int*)mask)[i] != 0u);
    else         t = (((const unsigned char*)mask)[i] != 0);
    g_bias[i] = t ? 0.0f : -1e30f;
}

// ---------------- fp32 -> bf16 hi/lo split ----------------
__global__ void split_kernel(const float* __restrict__ src,
                             __nv_bfloat16* __restrict__ hi,
                             __nv_bfloat16* __restrict__ lo, int n) {
    int i = blockIdx.x * blockDim.x + threadIdx.x;
    if (i >= n) return;
    float x = src[i];
    __nv_bfloat16 h = __float2bfloat16(x);
    hi[i] = h;
    lo[i] = __float2bfloat16(x - __bfloat162float(h));
}

// ---------------- mma.sync GEMM (unchanged from passing R12 kernel) -------
#define KTOT 1024
#define KC 32
#define PADW 40
#define PADW32 (PADW/2)
template <int MODE>
__global__ void __launch_bounds__(256, 2)
mma_gemm_kernel(const __nv_bfloat16* __restrict__ Ah,
                const __nv_bfloat16* __restrict__ Al,
                const __nv_bfloat16* __restrict__ Bh,
                const __nv_bfloat16* __restrict__ Bl,
                const float* __restrict__ bias,
                float* __restrict__ out) {
    __shared__ __nv_bfloat16 sA[2][128 * PADW];
    __shared__ __nv_bfloat16 sB[2][128 * PADW];

    const int tid = threadIdx.x;
    const int wid = tid >> 5, lane = tid & 31;
    const int wm = wid >> 1;
    const int wn = wid & 1;
    const int row0 = blockIdx.y * 128;
    const int col0 = blockIdx.x * 128;

    const __nv_bfloat16* srcA[2] = { Ah + (size_t)row0 * KTOT, Al + (size_t)row0 * KTOT };
    const __nv_bfloat16* srcB[2] = { Bh + (size_t)col0 * KTOT, Bl + (size_t)col0 * KTOT };

    float acc[2][8][4];
#pragma unroll
    for (int mt = 0; mt < 2; mt++)
#pragma unroll
        for (int nt = 0; nt < 8; nt++)
#pragma unroll
            for (int e = 0; e < 4; e++) acc[mt][nt][e] = 0.0f;

    const int r0 = lane >> 2;
    const int kw = lane & 3;

    for (int ch = 0; ch < KTOT / KC; ch++) {
        const int k0 = ch * KC;
        __syncthreads();
#pragma unroll
        for (int t = 0; t < 4; t++) {
            const __nv_bfloat16* src = (t < 2) ? srcA[t] : srcB[t - 2];
            uint4* dst = (uint4*)((t < 2) ? sA[t] : sB[t - 2]);
#pragma unroll
            for (int u = 0; u < 2; u++) {
                int idx = u * 256 + tid;
                int r = idx >> 2, c = idx & 3;
                dst[r * 5 + c] = *(const uint4*)(src + (size_t)r * KTOT + k0 + c * 8);
            }
        }
        __syncthreads();

#pragma unroll
        for (int ps = 0; ps < 3; ps++) {
            const int ia = (ps == 2) ? 1 : 0;
            const int ib = (ps == 1) ? 1 : 0;
            const uint32_t* wa = (const uint32_t*)sA[ia];
            const uint32_t* wb = (const uint32_t*)sB[ib];
#pragma unroll
            for (int ks = 0; ks < 2; ks++) {
                const int k8 = ks * 8;
                uint32_t af[2][4];
#pragma unroll
                for (int mt = 0; mt < 2; mt++) {
                    int rb = wm * 32 + mt * 16;
                    af[mt][0] = wa[(rb + r0)      * PADW32 + k8 + kw];
                    af[mt][1] = wa[(rb + r0 + 8)  * PADW32 + k8 + kw];
                    af[mt][2] = wa[(rb + r0)      * PADW32 + k8 + kw + 4];
                    af[mt][3] = wa[(rb + r0 + 8)  * PADW32 + k8 + kw + 4];
                }
#pragma unroll
                for (int nt = 0; nt < 8; nt++) {
                    int nb = wn * 64 + nt * 8;
                    uint32_t bf[2];
                    bf[0] = wb[(nb + r0) * PADW32 + k8 + kw];
                    bf[1] = wb[(nb + r0) * PADW32 + k8 + kw + 4];
#pragma unroll
                    for (int mt = 0; mt < 2; mt++)
                        mma_bf16_16816(acc[mt][nt], af[mt], bf);
                }
            }
        }
    }

#pragma unroll
    for (int mt = 0; mt < 2; mt++) {
#pragma unroll
        for (int e2 = 0; e2 < 2; e2++) {
            int row = row0 + wm * 32 + mt * 16 + (lane >> 2) + e2 * 8;
            const int b = row >> 11, s = row & 2047;
#pragma unroll
            for (int nt = 0; nt < 8; nt++) {
#pragma unroll
                for (int e1 = 0; e1 < 2; e1++) {
                    int col = col0 + wn * 64 + nt * 8 + 2 * (lane & 3) + e1;
                    float val = acc[mt][nt][e2 * 2 + e1] + bias[col];
                    if (MODE == 0) {
                        int h = col / 192;
                        int rem = col - h * 192;
                        int part = rem >> 6;
                        int d = rem & 63;
                        float* dst = (part == 0) ? g_Q : (part == 1) ? g_K : g_V;
                        dst[((size_t)(b * Hh + h) * Ss + s) * DH + d] = val;
                    } else {
                        out[(size_t)row * Dd + col] = val;
                    }
                }
            }
        }
    }
}

// ---------------- tensor-core flash attention -----------------------------
// 128 threads = 4 warps. Q-tile 64 (16 rows/warp), kv-tile 64, dh 64.
// S = QK^T via 3-pass hi/lo mma; softmax on register fragments;
// O += P V via 3-pass hi/lo mma (P packed from registers, V transposed smem).
// smem rows padded to 72 bf16 (36 words): frag reads (36*r0 + kw) conflict-free.
#define APAD 72
#define APADW 36
__global__ void __launch_bounds__(128)
attn_mma_kernel() {
    __shared__ __nv_bfloat16 sKh[64 * APAD], sKl[64 * APAD];
    __shared__ __nv_bfloat16 sVh[64 * APAD], sVl[64 * APAD];  // [d][kv]
    __shared__ float bs[64];

    const int tid = threadIdx.x;
    const int w = tid >> 5, lane = tid & 31;
    const int r0 = lane >> 2, kw = lane & 3, c2 = kw * 2;
    const int bh = blockIdx.y, b = bh >> 4, h = bh & 15;
    const int q0 = blockIdx.x * 64;

    const float* Kg = g_K + (size_t)bh * Ss * DH;
    const float* Vg = g_V + (size_t)bh * Ss * DH;
    const float slope = exp2f(-0.5f * (float)(h + 1));
    const float scale = 0.03125f;

    // Q fragments (hi/lo) in registers: a0..a3 per k16 step
    uint32_t qh[4][4], ql[4][4];
    {
        const int rowa = q0 + w * 16 + r0;
#pragma unroll
        for (int ks = 0; ks < 4; ks++)
#pragma unroll
            for (int f = 0; f < 4; f++) {
                int row = rowa + ((f & 1) ? 8 : 0);
                int col = ks * 16 + c2 + ((f >= 2) ? 8 : 0);
                float2 v = *(const float2*)(g_Q + ((size_t)bh * Ss + row) * DH + col);
                qh[ks][f] = pack2(v.x, v.y);
                ql[ks][f] = pack2(bflo(v.x), bflo(v.y));
            }
    }

    float m_[2], l_[2], o[8][4];
#pragma unroll
    for (int i = 0; i < 2; i++) { m_[i] = -3.0e38f; l_[i] = 0.0f; }
#pragma unroll
    for (int nt = 0; nt < 8; nt++)
#pragma unroll
        for (int e = 0; e < 4; e++) o[nt][e] = 0.0f;

    for (int t = 0; t < Ss / 64; t++) {
        __syncthreads();   // prior tile's fragment reads complete
        const float* Kt = Kg + (size_t)t * 64 * DH;
        const float* Vt = Vg + (size_t)t * 64 * DH;
        // K tile: natural layout [kv][d], bf16 hi/lo, padded rows
#pragma unroll
        for (int it = 0; it < 8; it++) {
            int idx = it * 128 + tid;
            int kv = idx >> 4, dv = idx & 15;
            float4 f = *(const float4*)(Kt + (size_t)kv * DH + dv * 4);
            uint2 wh = { pack2(f.x, f.y), pack2(f.z, f.w) };
            uint2 wl = { pack2(bflo(f.x), bflo(f.y)), pack2(bflo(f.z), bflo(f.w)) };
            *(uint2*)&((uint32_t*)sKh)[kv * APADW + dv * 2] = wh;
            *(uint2*)&((uint32_t*)sKl)[kv * APADW + dv * 2] = wl;
        }
        // V tile transposed: sV[d][kv]
#pragma unroll
        for (int it = 0; it < 8; it++) {
            int idx = it * 128 + tid;
            int d = idx & 63, kv4 = idx >> 6;
            float v0 = Vt[(size_t)(kv4 * 4 + 0) * DH + d];
            float v1 = Vt[(size_t)(kv4 * 4 + 1) * DH + d];
            float v2 = Vt[(size_t)(kv4 * 4 + 2) * DH + d];
            float v3 = Vt[(size_t)(kv4 * 4 + 3) * DH + d];
            ((uint32_t*)sVh)[d * APADW + kv4 * 2 + 0] = pack2(v0, v1);
            ((uint32_t*)sVh)[d * APADW + kv4 * 2 + 1] = pack2(v2, v3);
            ((uint32_t*)sVl)[d * APADW + kv4 * 2 + 0] = pack2(bflo(v0), bflo(v1));
            ((uint32_t*)sVl)[d * APADW + kv4 * 2 + 1] = pack2(bflo(v2), bflo(v3));
        }
        if (tid < 64) bs[tid] = g_bias[b * Ss + t * 64 + tid];
        __syncthreads();

        // S = Q K^T (3 passes)
        float sv[8][4];
#pragma unroll
        for (int nt = 0; nt < 8; nt++)
#pragma unroll
            for (int e = 0; e < 4; e++) sv[nt][e] = 0.0f;
#pragma unroll
        for (int ps = 0; ps < 3; ps++) {
            const uint32_t* B = (const uint32_t*)((ps == 1) ? sKl : sKh);
#pragma unroll
            for (int ks = 0; ks < 4; ks++) {
                const uint32_t* a = (ps == 2) ? ql[ks] : qh[ks];
#pragma unroll
                for (int nt = 0; nt < 8; nt++) {
                    uint32_t bf[2];
                    bf[0] = B[(nt * 8 + r0) * APADW + ks * 8 + kw];
                    bf[1] = B[(nt * 8 + r0) * APADW + ks * 8 + kw + 4];
                    mma_bf16_16816(sv[nt], a, bf);
                }
            }
        }

        // softmax on fragments (rows r0, r0+8 of this warp's 16)
#pragma unroll
        for (int e2 = 0; e2 < 2; e2++) {
            int q = q0 + w * 16 + r0 + e2 * 8;
            float mx = -3.0e38f;
#pragma unroll
            for (int nt = 0; nt < 8; nt++)
#pragma unroll
                for (int e1 = 0; e1 < 2; e1++) {
                    int kvl = nt * 8 + c2 + e1;
                    int kv = t * 64 + kvl;
                    float val = sv[nt][e2 * 2 + e1] * scale
                              + slope * (-fabsf((float)(q - kv))) + bs[kvl];
                    sv[nt][e2 * 2 + e1] = val;
                    mx = fmaxf(mx, val);
                }
            mx = fmaxf(mx, __shfl_xor_sync(0xffffffffu, mx, 1));
            mx = fmaxf(mx, __shfl_xor_sync(0xffffffffu, mx, 2));
            float newm = fmaxf(m_[e2], mx);
            float corr = __expf(m_[e2] - newm);
            float rsum = 0.0f;
#pragma unroll
            for (int nt = 0; nt < 8; nt++)
#pragma unroll
                for (int e1 = 0; e1 < 2; e1++) {
                    float p = __expf(sv[nt][e2 * 2 + e1] - newm);
                    sv[nt][e2 * 2 + e1] = p;
                    rsum += p;
                }
            rsum += __shfl_xor_sync(0xffffffffu, rsum, 1);
            rsum += __shfl_xor_sync(0xffffffffu, rsum, 2);
            l_[e2] = l_[e2] * corr + rsum;
            m_[e2] = newm;
#pragma unroll
            for (int nt = 0; nt < 8; nt++) {
                o[nt][e2 * 2 + 0] *= corr;
                o[nt][e2 * 2 + 1] *= corr;
            }
        }

        // pack P fragments: k16 step j = accumulator tiles 2j, 2j+1
        uint32_t pah[4][4], pal[4][4];
#pragma unroll
        for (int j = 0; j < 4; j++) {
            pah[j][0] = pack2(sv[2 * j][0], sv[2 * j][1]);
            pah[j][1] = pack2(sv[2 * j][2], sv[2 * j][3]);
            pah[j][2] = pack2(sv[2 * j + 1][0], sv[2 * j + 1][1]);
            pah[j][3] = pack2(sv[2 * j + 1][2], sv[2 * j + 1][3]);
            pal[j][0] = pack2(bflo(sv[2 * j][0]), bflo(sv[2 * j][1]));
            pal[j][1] = pack2(bflo(sv[2 * j][2]), bflo(sv[2 * j][3]));
            pal[j][2] = pack2(bflo(sv[2 * j + 1][0]), bflo(sv[2 * j + 1][1]));
            pal[j][3] = pack2(bflo(sv[2 * j + 1][2]), bflo(sv[2 * j + 1][3]));
        }

        // O += P V (3 passes)
#pragma unroll
        for (int ps = 0; ps < 3; ps++) {
            const uint32_t* B = (const uint32_t*)((ps == 1) ? sVl : sVh);
#pragma unroll
            for (int j = 0; j < 4; j++) {
                const uint32_t* a = (ps == 2) ? pal[j] : pah[j];
#pragma unroll
                for (int nt = 0; nt < 8; nt++) {
                    uint32_t bf[2];
                    bf[0] = B[(nt * 8 + r0) * APADW + j * 8 + kw];
                    bf[1] = B[(nt * 8 + r0) * APADW + j * 8 + kw + 4];
                    mma_bf16_16816(o[nt], a, bf);
                }
            }
        }
    }

    // epilogue: write Ch/Cl (bf16 hi/lo) directly -> proj GEMM input
#pragma unroll
    for (int e2 = 0; e2 < 2; e2++) {
        int s = q0 + w * 16 + r0 + e2 * 8;
        float inv = 1.0f / l_[e2];
        size_t base = ((size_t)(b * Ss + s)) * Dd + h * DH;
#pragma unroll
        for (int nt = 0; nt < 8; nt++) {
            float o0 = o[nt][e2 * 2 + 0] * inv;
            float o1 = o[nt][e2 * 2 + 1] * inv;
            size_t off = base + nt * 8 + c2;
            ((uint32_t*)g_Ch)[off >> 1] = pack2(o0, o1);
            ((uint32_t*)g_Cl)[off >> 1] = pack2(bflo(o0), bflo(o1));
        }
    }
}

// ---------------- launch ----------------
extern "C" void kernel_launch(void* const* d_in, const int* in_sizes, int n_in,
                              void* d_out, int out_size) {
    const float* inputs = (const float*)d_in[0];
    const void*  mask   = d_in[1];
    const float* Wqkv   = (const float*)d_in[2];
    const float* bqkv   = (const float*)d_in[3];
    const float* Wproj  = (const float*)d_in[4];
    const float* bproj  = (const float*)d_in[5];
    float* out = (float*)d_out;

    __nv_bfloat16 *pAh, *pAl, *pWQh, *pWQl, *pWPh, *pWPl, *pCh, *pCl;
    cudaGetSymbolAddress((void**)&pAh,  g_Ah);
    cudaGetSymbolAddress((void**)&pAl,  g_Al);
    cudaGetSymbolAddress((void**)&pWQh, g_WQh);
    cudaGetSymbolAddress((void**)&pWQl, g_WQl);
    cudaGetSymbolAddress((void**)&pWPh, g_WPh);
    cudaGetSymbolAddress((void**)&pWPl, g_WPl);
    cudaGetSymbolAddress((void**)&pCh,  g_Ch);
    cudaGetSymbolAddress((void**)&pCl,  g_Cl);

    detect_mask_kernel<<<1, 256>>>((const unsigned int*)mask);
    build_bias_kernel<<<(Bb * Ss + 255) / 256, 256>>>(mask);

    const int nA = Bb * Ss * Dd;
    const int nWQ = 3 * Dd * Dd;
    const int nWP = Dd * Dd;
    split_kernel<<<(nA + 255) / 256, 256>>>(inputs, pAh, pAl, nA);
    split_kernel<<<(nWQ + 255) / 256, 256>>>(Wqkv, pWQh, pWQl, nWQ);
    split_kernel<<<(nWP + 255) / 256, 256>>>(Wproj, pWPh, pWPl, nWP);

    mma_gemm_kernel<0><<<dim3(3 * Dd / 128, Bb * Ss / 128), 256>>>(
        pAh, pAl, pWQh, pWQl, bqkv, nullptr);

    attn_mma_kernel<<<dim3(Ss / 64, BHN), 128>>>();

    mma_gemm_kernel<1><<<dim3(Dd / 128, Bb * Ss / 128), 256>>>(
        pCh, pCl, pWPh, pWPl, bproj, out);
}

// round 15
// speedup vs baseline: 2.4842x; 1.1521x over previous
#include <cuda_runtime.h>
#include <cuda_bf16.h>
#include <math.h>
#include <stdint.h>

#define Bb 2
#define Ss 2048
#define Dd 1024
#define Hh 16
#define DH 64
#define BHN (Bb*Hh)

// ---------------- scratch (static device globals; no allocs) ----------------
__device__ float g_bias[Bb * Ss];
__device__ int   g_elem4;

// bf16 hi/lo planes
__device__ __nv_bfloat16 g_Ah[(size_t)Bb * Ss * Dd];
__device__ __nv_bfloat16 g_Al[(size_t)Bb * Ss * Dd];
__device__ __nv_bfloat16 g_WQh[(size_t)3 * Dd * Dd];
__device__ __nv_bfloat16 g_WQl[(size_t)3 * Dd * Dd];
__device__ __nv_bfloat16 g_WPh[(size_t)Dd * Dd];
__device__ __nv_bfloat16 g_WPl[(size_t)Dd * Dd];
__device__ __nv_bfloat16 g_Qh[(size_t)BHN * Ss * DH];   // [bh][s][d]
__device__ __nv_bfloat16 g_Ql[(size_t)BHN * Ss * DH];
__device__ __nv_bfloat16 g_Kh[(size_t)BHN * Ss * DH];   // [bh][s][d]
__device__ __nv_bfloat16 g_Kl[(size_t)BHN * Ss * DH];
__device__ __nv_bfloat16 g_Vth[(size_t)BHN * DH * Ss];  // transposed [bh][d][s]
__device__ __nv_bfloat16 g_Vtl[(size_t)BHN * DH * Ss];
__device__ __nv_bfloat16 g_Ch[(size_t)Bb * Ss * Dd];    // attn out hi
__device__ __nv_bfloat16 g_Cl[(size_t)Bb * Ss * Dd];    // attn out lo

// ---------------- helpers ----------------
__device__ __forceinline__ uint32_t pack2(float lo, float hi) {
    uint32_t a = (uint32_t)__bfloat16_as_ushort(__float2bfloat16(lo));
    uint32_t bq = (uint32_t)__bfloat16_as_ushort(__float2bfloat16(hi));
    return a | (bq << 16);
}
__device__ __forceinline__ float bflo(float x) {
    return x - __bfloat162float(__float2bfloat16(x));
}
__device__ __forceinline__ void mma_bf16_16816(float* d, const uint32_t* a,
                                               const uint32_t* b) {
    asm volatile(
        "mma.sync.aligned.m16n8k16.row.col.f32.bf16.bf16.f32 "
        "{%0,%1,%2,%3}, {%4,%5,%6,%7}, {%8,%9}, {%0,%1,%2,%3};"
        : "+f"(d[0]), "+f"(d[1]), "+f"(d[2]), "+f"(d[3])
        : "r"(a[0]), "r"(a[1]), "r"(a[2]), "r"(a[3]), "r"(b[0]), "r"(b[1]));
}

// ---------------- mask dtype detection ----------------
__global__ void detect_mask_kernel(const unsigned int* __restrict__ m) {
    __shared__ int bad;
    if (threadIdx.x == 0) bad = 0;
    __syncthreads();
    int loc = 0;
    for (int i = threadIdx.x; i < 1024; i += blockDim.x) {
        unsigned int w = m[i];
        if (!(w == 0u || w == 1u || w == 0x3f800000u)) loc = 1;
    }
    if (loc) atomicExch(&bad, 1);
    __syncthreads();
    if (threadIdx.x == 0) g_elem4 = bad ? 0 : 1;
}

__global__ void build_bias_kernel(const void* __restrict__ mask) {
    int i = blockIdx.x * blockDim.x + threadIdx.x;
    if (i >= Bb * Ss) return;
    bool t;
    if (g_elem4) t = (((const unsigned int*)mask)[i] != 0u);
    else         t = (((const unsigned char*)mask)[i] != 0);
    g_bias[i] = t ? 0.0f : -1e30f;
}

// ---------------- fp32 -> bf16 hi/lo split (float4 vectorized) ----------------
__global__ void split_kernel(const float4* __restrict__ src,
                             uint2* __restrict__ hi,
                             uint2* __restrict__ lo, int n4) {
    int i = blockIdx.x * blockDim.x + threadIdx.x;
    if (i >= n4) return;
    float4 x = src[i];
    uint2 h, l;
    h.x = pack2(x.x, x.y);  h.y = pack2(x.z, x.w);
    l.x = pack2(bflo(x.x), bflo(x.y));  l.y = pack2(bflo(x.z), bflo(x.w));
    hi[i] = h;
    lo[i] = l;
}

// ---------------- mma.sync GEMM (mainloop unchanged from R12/R13) -------
#define KTOT 1024
#define KC 32
#define PADW 40
#define PADW32 (PADW/2)
// MODE 0: QKV epilogue -> bf16 planes (Q/K row-major, V transposed). MODE 1: proj -> fp32 out.
template <int MODE>
__global__ void __launch_bounds__(256, 2)
mma_gemm_kernel(const __nv_bfloat16* __restrict__ Ah,
                const __nv_bfloat16* __restrict__ Al,
                const __nv_bfloat16* __restrict__ Bh,
                const __nv_bfloat16* __restrict__ Bl,
                const float* __restrict__ bias,
                float* __restrict__ out) {
    __shared__ __nv_bfloat16 sA[2][128 * PADW];
    __shared__ __nv_bfloat16 sB[2][128 * PADW];

    const int tid = threadIdx.x;
    const int wid = tid >> 5, lane = tid & 31;
    const int wm = wid >> 1;
    const int wn = wid & 1;
    const int row0 = blockIdx.y * 128;
    const int col0 = blockIdx.x * 128;

    const __nv_bfloat16* srcA[2] = { Ah + (size_t)row0 * KTOT, Al + (size_t)row0 * KTOT };
    const __nv_bfloat16* srcB[2] = { Bh + (size_t)col0 * KTOT, Bl + (size_t)col0 * KTOT };

    float acc[2][8][4];
#pragma unroll
    for (int mt = 0; mt < 2; mt++)
#pragma unroll
        for (int nt = 0; nt < 8; nt++)
#pragma unroll
            for (int e = 0; e < 4; e++) acc[mt][nt][e] = 0.0f;

    const int r0 = lane >> 2;
    const int kw = lane & 3;

    for (int ch = 0; ch < KTOT / KC; ch++) {
        const int k0 = ch * KC;
        __syncthreads();
#pragma unroll
        for (int t = 0; t < 4; t++) {
            const __nv_bfloat16* src = (t < 2) ? srcA[t] : srcB[t - 2];
            uint4* dst = (uint4*)((t < 2) ? sA[t] : sB[t - 2]);
#pragma unroll
            for (int u = 0; u < 2; u++) {
                int idx = u * 256 + tid;
                int r = idx >> 2, c = idx & 3;
                dst[r * 5 + c] = *(const uint4*)(src + (size_t)r * KTOT + k0 + c * 8);
            }
        }
        __syncthreads();

#pragma unroll
        for (int ps = 0; ps < 3; ps++) {
            const int ia = (ps == 2) ? 1 : 0;
            const int ib = (ps == 1) ? 1 : 0;
            const uint32_t* wa = (const uint32_t*)sA[ia];
            const uint32_t* wb = (const uint32_t*)sB[ib];
#pragma unroll
            for (int ks = 0; ks < 2; ks++) {
                const int k8 = ks * 8;
                uint32_t af[2][4];
#pragma unroll
                for (int mt = 0; mt < 2; mt++) {
                    int rb = wm * 32 + mt * 16;
                    af[mt][0] = wa[(rb + r0)      * PADW32 + k8 + kw];
                    af[mt][1] = wa[(rb + r0 + 8)  * PADW32 + k8 + kw];
                    af[mt][2] = wa[(rb + r0)      * PADW32 + k8 + kw + 4];
                    af[mt][3] = wa[(rb + r0 + 8)  * PADW32 + k8 + kw + 4];
                }
#pragma unroll
                for (int nt = 0; nt < 8; nt++) {
                    int nb = wn * 64 + nt * 8;
                    uint32_t bf[2];
                    bf[0] = wb[(nb + r0) * PADW32 + k8 + kw];
                    bf[1] = wb[(nb + r0) * PADW32 + k8 + kw + 4];
#pragma unroll
                    for (int mt = 0; mt < 2; mt++)
                        mma_bf16_16816(acc[mt][nt], af[mt], bf);
                }
            }
        }
    }

#pragma unroll
    for (int mt = 0; mt < 2; mt++) {
#pragma unroll
        for (int e2 = 0; e2 < 2; e2++) {
            int row = row0 + wm * 32 + mt * 16 + (lane >> 2) + e2 * 8;
            const int b = row >> 11, s = row & 2047;
#pragma unroll
            for (int nt = 0; nt < 8; nt++) {
                int col = col0 + wn * 64 + nt * 8 + 2 * (lane & 3);
                float v0 = acc[mt][nt][e2 * 2 + 0] + bias[col];
                float v1 = acc[mt][nt][e2 * 2 + 1] + bias[col + 1];
                if (MODE == 0) {
                    int h = col / 192;
                    int rem = col - h * 192;
                    int part = rem >> 6;
                    int d = rem & 63;
                    int bh = b * Hh + h;
                    if (part < 2) {
                        size_t off = ((size_t)bh * Ss + s) * DH + d;
                        __nv_bfloat16* ph = (part == 0) ? g_Qh : g_Kh;
                        __nv_bfloat16* pl = (part == 0) ? g_Ql : g_Kl;
                        *(uint32_t*)&ph[off] = pack2(v0, v1);
                        *(uint32_t*)&pl[off] = pack2(bflo(v0), bflo(v1));
                    } else {
                        size_t off = ((size_t)bh * DH + d) * Ss + s;
                        g_Vth[off]      = __float2bfloat16(v0);
                        g_Vth[off + Ss] = __float2bfloat16(v1);
                        g_Vtl[off]      = __float2bfloat16(bflo(v0));
                        g_Vtl[off + Ss] = __float2bfloat16(bflo(v1));
                    }
                } else {
                    out[(size_t)row * Dd + col]     = v0;
                    out[(size_t)row * Dd + col + 1] = v1;
                }
            }
        }
    }
}

// ---------------- tensor-core flash attention (bf16-plane inputs) ---------
// 128 threads = 4 warps. Q-tile 64 (16 rows/warp), kv-tile 64, dh 64.
// Validated R13 fragment layouts; smem fills are now pure uint4 copies.
#define APAD 72
#define APADW 36
__global__ void __launch_bounds__(128)
attn_mma_kernel() {
    __shared__ __nv_bfloat16 sKh[64 * APAD], sKl[64 * APAD];  // [kv][d]
    __shared__ __nv_bfloat16 sVh[64 * APAD], sVl[64 * APAD];  // [d][kv]
    __shared__ float bs[64];

    const int tid = threadIdx.x;
    const int w = tid >> 5, lane = tid & 31;
    const int r0 = lane >> 2, kw = lane & 3, c2 = kw * 2;
    const int bh = blockIdx.y, b = bh >> 4, h = bh & 15;
    const int q0 = blockIdx.x * 64;

    const __nv_bfloat16* Khg = g_Kh + (size_t)bh * Ss * DH;
    const __nv_bfloat16* Klg = g_Kl + (size_t)bh * Ss * DH;
    const __nv_bfloat16* Vhg = g_Vth + (size_t)bh * DH * Ss;
    const __nv_bfloat16* Vlg = g_Vtl + (size_t)bh * DH * Ss;
    const float slope = exp2f(-0.5f * (float)(h + 1));
    const float scale = 0.03125f;

    // Q fragments: direct uint32 loads from planes
    uint32_t qh[4][4], ql[4][4];
    {
        const int rowa = q0 + w * 16 + r0;
#pragma unroll
        for (int ks = 0; ks < 4; ks++)
#pragma unroll
            for (int f = 0; f < 4; f++) {
                int row = rowa + ((f & 1) ? 8 : 0);
                int col = ks * 16 + c2 + ((f >= 2) ? 8 : 0);
                size_t off = ((size_t)bh * Ss + row) * DH + col;
                qh[ks][f] = *(const uint32_t*)&g_Qh[off];
                ql[ks][f] = *(const uint32_t*)&g_Ql[off];
            }
    }

    float m_[2], l_[2], o[8][4];
#pragma unroll
    for (int i = 0; i < 2; i++) { m_[i] = -3.0e38f; l_[i] = 0.0f; }
#pragma unroll
    for (int nt = 0; nt < 8; nt++)
#pragma unroll
        for (int e = 0; e < 4; e++) o[nt][e] = 0.0f;

    for (int t = 0; t < Ss / 64; t++) {
        __syncthreads();
        // K tiles: [kv][d] rows; 512 uint4 per plane, 4 iters each
#pragma unroll
        for (int it = 0; it < 4; it++) {
            int idx = it * 128 + tid;
            int kv = idx >> 3, dv = idx & 7;
            size_t soff = (size_t)(t * 64 + kv) * DH + dv * 8;
            *(uint4*)&((uint32_t*)sKh)[kv * APADW + dv * 4] = *(const uint4*)&Khg[soff];
            *(uint4*)&((uint32_t*)sKl)[kv * APADW + dv * 4] = *(const uint4*)&Klg[soff];
        }
        // V tiles: transposed source [d][s]; rows d, cols kv
#pragma unroll
        for (int it = 0; it < 4; it++) {
            int idx = it * 128 + tid;
            int d = idx >> 3, sv8 = idx & 7;
            size_t soff = (size_t)d * Ss + t * 64 + sv8 * 8;
            *(uint4*)&((uint32_t*)sVh)[d * APADW + sv8 * 4] = *(const uint4*)&Vhg[soff];
            *(uint4*)&((uint32_t*)sVl)[d * APADW + sv8 * 4] = *(const uint4*)&Vlg[soff];
        }
        if (tid < 64) bs[tid] = g_bias[b * Ss + t * 64 + tid];
        __syncthreads();

        // S = Q K^T (3 passes)
        float sv[8][4];
#pragma unroll
        for (int nt = 0; nt < 8; nt++)
#pragma unroll
            for (int e = 0; e < 4; e++) sv[nt][e] = 0.0f;
#pragma unroll
        for (int ps = 0; ps < 3; ps++) {
            const uint32_t* B = (const uint32_t*)((ps == 1) ? sKl : sKh);
#pragma unroll
            for (int ks = 0; ks < 4; ks++) {
                const uint32_t* a = (ps == 2) ? ql[ks] : qh[ks];
#pragma unroll
                for (int nt = 0; nt < 8; nt++) {
                    uint32_t bf[2];
                    bf[0] = B[(nt * 8 + r0) * APADW + ks * 8 + kw];
                    bf[1] = B[(nt * 8 + r0) * APADW + ks * 8 + kw + 4];
                    mma_bf16_16816(sv[nt], a, bf);
                }
            }
        }

        // softmax on fragments
#pragma unroll
        for (int e2 = 0; e2 < 2; e2++) {
            int q = q0 + w * 16 + r0 + e2 * 8;
            float mx = -3.0e38f;
#pragma unroll
            for (int nt = 0; nt < 8; nt++)
#pragma unroll
                for (int e1 = 0; e1 < 2; e1++) {
                    int kvl = nt * 8 + c2 + e1;
                    int kv = t * 64 + kvl;
                    float val = sv[nt][e2 * 2 + e1] * scale
                              + slope * (-fabsf((float)(q - kv))) + bs[kvl];
                    sv[nt][e2 * 2 + e1] = val;
                    mx = fmaxf(mx, val);
                }
            mx = fmaxf(mx, __shfl_xor_sync(0xffffffffu, mx, 1));
            mx = fmaxf(mx, __shfl_xor_sync(0xffffffffu, mx, 2));
            float newm = fmaxf(m_[e2], mx);
            float corr = __expf(m_[e2] - newm);
            float rsum = 0.0f;
#pragma unroll
            for (int nt = 0; nt < 8; nt++)
#pragma unroll
                for (int e1 = 0; e1 < 2; e1++) {
                    float p = __expf(sv[nt][e2 * 2 + e1] - newm);
                    sv[nt][e2 * 2 + e1] = p;
                    rsum += p;
                }
            rsum += __shfl_xor_sync(0xffffffffu, rsum, 1);
            rsum += __shfl_xor_sync(0xffffffffu, rsum, 2);
            l_[e2] = l_[e2] * corr + rsum;
            m_[e2] = newm;
#pragma unroll
            for (int nt = 0; nt < 8; nt++) {
                o[nt][e2 * 2 + 0] *= corr;
                o[nt][e2 * 2 + 1] *= corr;
            }
        }

        // pack P fragments
        uint32_t pah[4][4], pal[4][4];
#pragma unroll
        for (int j = 0; j < 4; j++) {
            pah[j][0] = pack2(sv[2 * j][0], sv[2 * j][1]);
            pah[j][1] = pack2(sv[2 * j][2], sv[2 * j][3]);
            pah[j][2] = pack2(sv[2 * j + 1][0], sv[2 * j + 1][1]);
            pah[j][3] = pack2(sv[2 * j + 1][2], sv[2 * j + 1][3]);
            pal[j][0] = pack2(bflo(sv[2 * j][0]), bflo(sv[2 * j][1]));
            pal[j][1] = pack2(bflo(sv[2 * j][2]), bflo(sv[2 * j][3]));
            pal[j][2] = pack2(bflo(sv[2 * j + 1][0]), bflo(sv[2 * j + 1][1]));
            pal[j][3] = pack2(bflo(sv[2 * j + 1][2]), bflo(sv[2 * j + 1][3]));
        }

        // O += P V (3 passes)
#pragma unroll
        for (int ps = 0; ps < 3; ps++) {
            const uint32_t* B = (const uint32_t*)((ps == 1) ? sVl : sVh);
#pragma unroll
            for (int j = 0; j < 4; j++) {
                const uint32_t* a = (ps == 2) ? pal[j] : pah[j];
#pragma unroll
                for (int nt = 0; nt < 8; nt++) {
                    uint32_t bf[2];
                    bf[0] = B[(nt * 8 + r0) * APADW + j * 8 + kw];
                    bf[1] = B[(nt * 8 + r0) * APADW + j * 8 + kw + 4];
                    mma_bf16_16816(o[nt], a, bf);
                }
            }
        }
    }

    // epilogue: write Ch/Cl (bf16 hi/lo) -> proj GEMM input
#pragma unroll
    for (int e2 = 0; e2 < 2; e2++) {
        int s = q0 + w * 16 + r0 + e2 * 8;
        float inv = 1.0f / l_[e2];
        size_t base = ((size_t)(b * Ss + s)) * Dd + h * DH;
#pragma unroll
        for (int nt = 0; nt < 8; nt++) {
            float o0 = o[nt][e2 * 2 + 0] * inv;
            float o1 = o[nt][e2 * 2 + 1] * inv;
            size_t off = base + nt * 8 + c2;
            ((uint32_t*)g_Ch)[off >> 1] = pack2(o0, o1);
            ((uint32_t*)g_Cl)[off >> 1] = pack2(bflo(o0), bflo(o1));
        }
    }
}

// ---------------- launch ----------------
extern "C" void kernel_launch(void* const* d_in, const int* in_sizes, int n_in,
                              void* d_out, int out_size) {
    const float* inputs = (const float*)d_in[0];
    const void*  mask   = d_in[1];
    const float* Wqkv   = (const float*)d_in[2];
    const float* bqkv   = (const float*)d_in[3];
    const float* Wproj  = (const float*)d_in[4];
    const float* bproj  = (const float*)d_in[5];
    float* out = (float*)d_out;

    __nv_bfloat16 *pAh, *pAl, *pWQh, *pWQl, *pWPh, *pWPl, *pCh, *pCl;
    cudaGetSymbolAddress((void**)&pAh,  g_Ah);
    cudaGetSymbolAddress((void**)&pAl,  g_Al);
    cudaGetSymbolAddress((void**)&pWQh, g_WQh);
    cudaGetSymbolAddress((void**)&pWQl, g_WQl);
    cudaGetSymbolAddress((void**)&pWPh, g_WPh);
    cudaGetSymbolAddress((void**)&pWPl, g_WPl);
    cudaGetSymbolAddress((void**)&pCh,  g_Ch);
    cudaGetSymbolAddress((void**)&pCl,  g_Cl);

    detect_mask_kernel<<<1, 256>>>((const unsigned int*)mask);
    build_bias_kernel<<<(Bb * Ss + 255) / 256, 256>>>(mask);

    const int nA4 = Bb * Ss * Dd / 4;
    const int nWQ4 = 3 * Dd * Dd / 4;
    const int nWP4 = Dd * Dd / 4;
    split_kernel<<<(nA4 + 255) / 256, 256>>>((const float4*)inputs,
                                             (uint2*)pAh, (uint2*)pAl, nA4);
    split_kernel<<<(nWQ4 + 255) / 256, 256>>>((const float4*)Wqkv,
                                              (uint2*)pWQh, (uint2*)pWQl, nWQ4);
    split_kernel<<<(nWP4 + 255) / 256, 256>>>((const float4*)Wproj,
                                              (uint2*)pWPh, (uint2*)pWPl, nWP4);

    mma_gemm_kernel<0><<<dim3(3 * Dd / 128, Bb * Ss / 128), 256>>>(
        pAh, pAl, pWQh, pWQl, bqkv, nullptr);

    attn_mma_kernel<<<dim3(Ss / 64, BHN), 128>>>();

    mma_gemm_kernel<1><<<dim3(Dd / 128, Bb * Ss / 128), 256>>>(
        pCh, pCl, pWPh, pWPl, bproj, out);
}